// round 14
// baseline (speedup 1.0000x reference)
#include <cuda_runtime.h>
#include <cuda_bf16.h>
#include <mma.h>
#include <math.h>
#include <stdint.h>

// ---------------- problem constants ----------------
#define BZ    8
#define HH    56
#define WW    56
#define HWP   3136
#define RR    25088       // BZ*HWP rows
#define C0N   256
#define C1N   512
#define C2N   1024
#define CIN   1794
#define DOUT  448
#define NC    3136

#define KBP   1856        // gemmB K padded (29*64)
#define XSTR  (2*KBP)     // hi plane + lo plane
#define KCP   448         // gemmC K (7*64)
#define PSTR  (2*KCP)     // phi / C stride (hi+lo planes)

#define SEG_B (KBP/64)    // 29
#define SEG_C (KCP/64)    // 7
#define NCH_B (3*SEG_B)   // 87

// smem layout (bytes) — R4's offsets and allocation sizes
#define FB_A0  0
#define FB_A1  18432
#define FB_B0  36864
#define FB_B1  46080
#define FB_CS  55296            // 128*72*4 = 36864
#define FB_AUX 92160            // bias / cent2 staging (64 floats)
#define B_SMEM 148480
#define C_SMEM 98304

// ---------------- scratch ----------------
__device__ float g_pool1[BZ * C1N * 28 * 28];
__device__ float g_pool2[BZ * C2N * 14 * 14];
__device__ float g_feat2[RR];
__device__ float g_cent2[NC];
__device__ __align__(16) unsigned short gXt[(size_t)RR * XSTR];
__device__ __align__(16) unsigned short gWt[(size_t)DOUT * XSTR];
__device__ __align__(16) unsigned short gPhiT[(size_t)RR * PSTR];
__device__ __align__(16) unsigned short gCt[(size_t)NC * PSTR];

// ---------------- helpers ----------------
__device__ __forceinline__ unsigned short f2bf(float x) {
    __nv_bfloat16 h = __float2bfloat16(x);
    unsigned short u; memcpy(&u, &h, 2); return u;
}
__device__ __forceinline__ float bf2f(unsigned short u) {
    return __uint_as_float((unsigned)u << 16);
}
__device__ __forceinline__ void ins3(float v, float& a, float& b, float& c) {
    if (v < c) {
        if (v < b) { c = b; if (v < a) { b = a; a = v; } else b = v; }
        else c = v;
    }
}
// top-8 insertion over sorted register array (ascending)
__device__ __forceinline__ void ins8(uint32_t v, uint32_t* s) {
    if (v < s[7]) {
        s[7] = v;
        #pragma unroll
        for (int i = 7; i > 0; i--) {
            if (s[i] < s[i - 1]) { uint32_t t = s[i]; s[i] = s[i - 1]; s[i - 1] = t; }
        }
    }
}
// unpack bf16x2 word -> two floats
__device__ __forceinline__ float2 unpk(uint32_t w) {
    return make_float2(__uint_as_float(w << 16), __uint_as_float(w & 0xFFFF0000u));
}

__device__ __forceinline__ float bilin(const float* __restrict__ ch, int S, float u, float v) {
    int y0 = (int)floorf(u); float fy = u - (float)y0;
    int x0 = (int)floorf(v); float fx = v - (float)x0;
    int y0c = min(max(y0, 0), S - 1);
    int y1c = min(max(y0 + 1, 0), S - 1);
    int x0c = min(max(x0, 0), S - 1);
    int x1c = min(max(x0 + 1, 0), S - 1);
    float a = ch[y0c * S + x0c], b = ch[y0c * S + x1c];
    float c = ch[y1c * S + x0c], d = ch[y1c * S + x1c];
    return (1.f - fy) * ((1.f - fx) * a + fx * b) + fy * ((1.f - fx) * c + fx * d);
}

// stage NROWS x 64 bf16 into padded stride-72 smem (LDG+STS)
template<int NROWS>
__device__ __forceinline__ void fstage(const unsigned short* __restrict__ src,
                                       size_t rstride, unsigned short* dst, int tid) {
    #pragma unroll
    for (int s = 0; s < NROWS * 8 / 256; s++) {
        int l = tid + s * 256;
        int row = l >> 3, c8 = l & 7;
        uint4 v = *(const uint4*)(src + (size_t)row * rstride + c8 * 8);
        *(uint4*)(dst + row * 72 + c8 * 8) = v;
    }
}

// ---------------- stage 1: pools for p1/p2 ----------------
__global__ void pool_kernel(const float* __restrict__ in, int total, int S, int which) {
    int idx = blockIdx.x * 256 + threadIdx.x;
    if (idx >= total) return;
    int x = idx % S, y = (idx / S) % S, bc = idx / (S * S);
    const float* p = in + (size_t)bc * S * S;
    float s = 0.f;
    #pragma unroll
    for (int dy = -1; dy <= 1; dy++) {
        int yy = y + dy; if ((unsigned)yy >= (unsigned)S) continue;
        #pragma unroll
        for (int dx = -1; dx <= 1; dx++) {
            int xx = x + dx; if ((unsigned)xx >= (unsigned)S) continue;
            s += p[yy * S + xx];
        }
    }
    (which ? g_pool2 : g_pool1)[idx] = s * (1.f / 9.f);
}

// ---------------- stage 2: weight/center packing ----------------
__global__ void prepW_kernel(const float* __restrict__ w) {
    int idx = blockIdx.x * 256 + threadIdx.x;
    if (idx >= DOUT * KBP) return;
    int o = idx / KBP, k = idx - o * KBP;
    float v = (k < CIN) ? w[o * CIN + k] : 0.f;
    unsigned short h = f2bf(v);
    gWt[(size_t)o * XSTR + k] = h;
    gWt[(size_t)o * XSTR + KBP + k] = f2bf(v - bf2f(h));
}

__global__ void prepC_kernel(const float* __restrict__ Cmat) {
    __shared__ float s[64][65];
    int n0 = blockIdx.x * 64;
    int k0 = blockIdx.y * 64;
    int tid = threadIdx.x;
    #pragma unroll
    for (int it = 0; it < 16; it++) {
        int l = tid + it * 256;
        int kk = l >> 6, nn = l & 63;
        s[kk][nn] = Cmat[(size_t)(k0 + kk) * NC + n0 + nn];
    }
    __syncthreads();
    #pragma unroll
    for (int it = 0; it < 2; it++) {
        int sg = tid + it * 256;
        int nn = sg >> 3, c8 = (sg & 7) * 8;
        unsigned hw[4], lw[4];
        #pragma unroll
        for (int j = 0; j < 8; j += 2) {
            float v0 = s[c8 + j][nn], v1 = s[c8 + j + 1][nn];
            unsigned short h0 = f2bf(v0), h1 = f2bf(v1);
            unsigned short l0 = f2bf(v0 - bf2f(h0)), l1 = f2bf(v1 - bf2f(h1));
            hw[j >> 1] = (unsigned)h0 | ((unsigned)h1 << 16);
            lw[j >> 1] = (unsigned)l0 | ((unsigned)l1 << 16);
        }
        size_t base = (size_t)(n0 + nn) * PSTR + k0 + c8;
        *(uint4*)(gCt + base)       = make_uint4(hw[0], hw[1], hw[2], hw[3]);
        *(uint4*)(gCt + base + KCP) = make_uint4(lw[0], lw[1], lw[2], lw[3]);
    }
}

__global__ void cent2_kernel(const float* __restrict__ Cmat) {
    int gid = blockIdx.x * 256 + threadIdx.x;
    int n = gid >> 3, part = gid & 7;
    if (n >= NC) return;
    float s = 0.f;
    for (int o = part; o < DOUT; o += 8) {
        float v = Cmat[(size_t)o * NC + n];
        s = fmaf(v, v, s);
    }
    s += __shfl_xor_sync(0xFFFFFFFFu, s, 1);
    s += __shfl_xor_sync(0xFFFFFFFFu, s, 2);
    s += __shfl_xor_sync(0xFFFFFFFFu, s, 4);
    if (part == 0) g_cent2[n] = s;
}

// ---------------- stage 3: build X row-major bf16 hi/lo via smem transpose ----------------
__global__ void buildx_kernel(const float* __restrict__ p0) {
    __shared__ float s[64][65];
    int rt0 = blockIdx.x * 64;
    int kt0 = blockIdx.y * 64;
    int tid = threadIdx.x;
    int rr = tid & 63;
    int r = rt0 + rr;
    int b = r / HWP;
    int pix = r - b * HWP;
    int h = pix / WW, w = pix - h * WW;

    #pragma unroll 1
    for (int i = 0; i < 16; i++) {
        int kk = (tid >> 6) * 16 + i;
        int k = kt0 + kk;
        float val;
        if (k < C0N) {
            const float* p = p0 + (size_t)(b * C0N + k) * HWP;
            float acc = 0.f;
            #pragma unroll
            for (int dy = -1; dy <= 1; dy++) {
                int y = h + dy; if ((unsigned)y >= (unsigned)HH) continue;
                #pragma unroll
                for (int dx = -1; dx <= 1; dx++) {
                    int x = w + dx; if ((unsigned)x >= (unsigned)WW) continue;
                    acc += p[y * WW + x];
                }
            }
            val = acc * (1.f / 9.f);
        } else if (k < C0N + C1N) {
            const float* ch = g_pool1 + (size_t)(b * C1N + (k - C0N)) * 784;
            val = bilin(ch, 28, h * 0.5f - 0.25f, w * 0.5f - 0.25f);
        } else if (k < C0N + C1N + C2N) {
            const float* ch = g_pool2 + (size_t)(b * C2N + (k - C0N - C1N)) * 196;
            val = bilin(ch, 14, h * 0.25f - 0.375f, w * 0.25f - 0.375f);
        } else if (k == 1792) {
            val = (float)h * (2.f / 55.f) - 1.f;
        } else if (k == 1793) {
            val = (float)w * (2.f / 55.f) - 1.f;
        } else {
            val = 0.f;
        }
        s[kk][rr] = val;
    }
    __syncthreads();

    #pragma unroll
    for (int it = 0; it < 2; it++) {
        int sg = tid + it * 256;
        int row = sg >> 3, c8 = (sg & 7) * 8;
        unsigned hw[4], lw[4];
        #pragma unroll
        for (int j = 0; j < 8; j += 2) {
            float v0 = s[c8 + j][row], v1 = s[c8 + j + 1][row];
            unsigned short h0 = f2bf(v0), h1 = f2bf(v1);
            unsigned short l0 = f2bf(v0 - bf2f(h0)), l1 = f2bf(v1 - bf2f(h1));
            hw[j >> 1] = (unsigned)h0 | ((unsigned)h1 << 16);
            lw[j >> 1] = (unsigned)l0 | ((unsigned)l1 << 16);
        }
        size_t base = (size_t)(rt0 + row) * XSTR + kt0 + c8;
        *(uint4*)(gXt + base)       = make_uint4(hw[0], hw[1], hw[2], hw[3]);
        *(uint4*)(gXt + base + KBP) = make_uint4(lw[0], lw[1], lw[2], lw[3]);
    }
}

// ==================================================================
// GEMM-B (R4-faithful): phi = X * W^T + bias; fused feat2 + bf16
// hi/lo store. block 128x64, 7 n-tiles, warp tile 32x32.
// ==================================================================
__global__ void __launch_bounds__(256)
gemmB_kernel(const float* __restrict__ bias) {
    using namespace nvcuda;
    extern __shared__ char smc[];
    float* Cs = (float*)(smc + FB_CS);
    float* biasS = (float*)(smc + FB_AUX);
    unsigned short* Abuf[2] = {(unsigned short*)(smc + FB_A0), (unsigned short*)(smc + FB_A1)};
    unsigned short* Bbuf[2] = {(unsigned short*)(smc + FB_B0), (unsigned short*)(smc + FB_B1)};
    int tid = threadIdx.x, wid = tid >> 5;
    int wm = wid & 3, wn = wid >> 2;
    int r0 = blockIdx.x * 128;
    float ss = 0.f;

    #pragma unroll 1
    for (int nt = 0; nt < DOUT / 64; nt++) {
        int n0 = nt * 64;
        if (tid < 64) biasS[tid] = bias[n0 + tid];

        wmma::fragment<wmma::accumulator, 16, 16, 16, float> cf[2][2];
        #pragma unroll
        for (int i = 0; i < 2; i++)
            #pragma unroll
            for (int j = 0; j < 2; j++) wmma::fill_fragment(cf[i][j], 0.f);

        fstage<128>(gXt + (size_t)r0 * XSTR, XSTR, Abuf[0], tid);
        fstage<64>(gWt + (size_t)n0 * XSTR, XSTR, Bbuf[0], tid);
        __syncthreads();

        #pragma unroll 1
        for (int c = 0; c < NCH_B; c++) {
            if (c + 1 < NCH_B) {
                int c1 = c + 1;
                int seg = c1 / SEG_B;
                int kb = (c1 - seg * SEG_B) * 64;
                int pa = (seg == 2) ? KBP : 0;
                int pb = (seg == 1) ? KBP : 0;
                fstage<128>(gXt + (size_t)r0 * XSTR + pa + kb, XSTR, Abuf[c1 & 1], tid);
                fstage<64>(gWt + (size_t)n0 * XSTR + pb + kb, XSTR, Bbuf[c1 & 1], tid);
            }
            const __nv_bfloat16* Ap = (const __nv_bfloat16*)Abuf[c & 1];
            const __nv_bfloat16* Bp = (const __nv_bfloat16*)Bbuf[c & 1];
            #pragma unroll
            for (int ks = 0; ks < 4; ks++) {
                wmma::fragment<wmma::matrix_b, 16, 16, 16, __nv_bfloat16, wmma::col_major> bf[2];
                wmma::load_matrix_sync(bf[0], Bp + (wn * 32) * 72 + ks * 16, 72);
                wmma::load_matrix_sync(bf[1], Bp + (wn * 32 + 16) * 72 + ks * 16, 72);
                #pragma unroll
                for (int i = 0; i < 2; i++) {
                    wmma::fragment<wmma::matrix_a, 16, 16, 16, __nv_bfloat16, wmma::row_major> af;
                    wmma::load_matrix_sync(af, Ap + (wm * 32 + i * 16) * 72 + ks * 16, 72);
                    wmma::mma_sync(cf[i][0], af, bf[0], cf[i][0]);
                    wmma::mma_sync(cf[i][1], af, bf[1], cf[i][1]);
                }
            }
            __syncthreads();
        }

        #pragma unroll
        for (int i = 0; i < 2; i++)
            #pragma unroll
            for (int j = 0; j < 2; j++)
                wmma::store_matrix_sync(Cs + (wm * 32 + i * 16) * 72 + wn * 32 + j * 16,
                                        cf[i][j], 72, wmma::mem_row_major);
        __syncthreads();

        if (tid < 128) {
            const float* crow = Cs + tid * 72;
            size_t r = (size_t)r0 + tid;
            unsigned hw[32], lw[32];
            #pragma unroll
            for (int j = 0; j < 64; j += 2) {
                float v0 = crow[j] + biasS[j];
                float v1 = crow[j + 1] + biasS[j + 1];
                ss = fmaf(v0, v0, ss);
                ss = fmaf(v1, v1, ss);
                unsigned short h0 = f2bf(v0), h1 = f2bf(v1);
                unsigned short l0 = f2bf(v0 - bf2f(h0)), l1 = f2bf(v1 - bf2f(h1));
                hw[j >> 1] = (unsigned)h0 | ((unsigned)h1 << 16);
                lw[j >> 1] = (unsigned)l0 | ((unsigned)l1 << 16);
            }
            uint4* dh = (uint4*)(gPhiT + r * PSTR + n0);
            uint4* dl = (uint4*)(gPhiT + r * PSTR + KCP + n0);
            #pragma unroll
            for (int q = 0; q < 8; q++) {
                dh[q] = make_uint4(hw[q * 4], hw[q * 4 + 1], hw[q * 4 + 2], hw[q * 4 + 3]);
                dl[q] = make_uint4(lw[q * 4], lw[q * 4 + 1], lw[q * 4 + 2], lw[q * 4 + 3]);
            }
        }
        __syncthreads();
    }
    if (tid < 128) g_feat2[r0 + tid] = ss;
}

// ==================================================================
// GEMM-C: approximate selection (phi_hi x C_hi only, 7 chunks/tile)
// with per-row top-8 candidates, then EXACT rescoring of the 8
// candidates (phi hi+lo, C hi+lo) + softmin.
// ==================================================================
__global__ void __launch_bounds__(256)
gemmC_kernel(float* __restrict__ out) {
    using namespace nvcuda;
    extern __shared__ char smc[];
    float* Cs = (float*)(smc + FB_CS);
    float* c2S = (float*)(smc + FB_AUX);
    unsigned short* Abuf[2] = {(unsigned short*)(smc + FB_A0), (unsigned short*)(smc + FB_A1)};
    unsigned short* Bbuf[2] = {(unsigned short*)(smc + FB_B0), (unsigned short*)(smc + FB_B1)};
    int tid = threadIdx.x, wid = tid >> 5;
    int wm = wid & 3, wn = wid >> 2;
    int r0 = blockIdx.x * 128;

    uint32_t s8[8];
    #pragma unroll
    for (int i = 0; i < 8; i++) s8[i] = 0xFFFFFFFFu;

    #pragma unroll 1
    for (int nt = 0; nt < NC / 64; nt++) {
        int n0 = nt * 64;
        if (tid < 64) c2S[tid] = g_cent2[n0 + tid];

        wmma::fragment<wmma::accumulator, 16, 16, 16, float> cf[2][2];
        #pragma unroll
        for (int i = 0; i < 2; i++)
            #pragma unroll
            for (int j = 0; j < 2; j++) wmma::fill_fragment(cf[i][j], 0.f);

        fstage<128>(gPhiT + (size_t)r0 * PSTR, PSTR, Abuf[0], tid);
        fstage<64>(gCt + (size_t)n0 * PSTR, PSTR, Bbuf[0], tid);
        __syncthreads();

        #pragma unroll 1
        for (int c = 0; c < SEG_C; c++) {
            if (c + 1 < SEG_C) {
                int kb = (c + 1) * 64;
                fstage<128>(gPhiT + (size_t)r0 * PSTR + kb, PSTR, Abuf[(c + 1) & 1], tid);
                fstage<64>(gCt + (size_t)n0 * PSTR + kb, PSTR, Bbuf[(c + 1) & 1], tid);
            }
            const __nv_bfloat16* Ap = (const __nv_bfloat16*)Abuf[c & 1];
            const __nv_bfloat16* Bp = (const __nv_bfloat16*)Bbuf[c & 1];
            #pragma unroll
            for (int ks = 0; ks < 4; ks++) {
                wmma::fragment<wmma::matrix_b, 16, 16, 16, __nv_bfloat16, wmma::col_major> bf[2];
                wmma::load_matrix_sync(bf[0], Bp + (wn * 32) * 72 + ks * 16, 72);
                wmma::load_matrix_sync(bf[1], Bp + (wn * 32 + 16) * 72 + ks * 16, 72);
                #pragma unroll
                for (int i = 0; i < 2; i++) {
                    wmma::fragment<wmma::matrix_a, 16, 16, 16, __nv_bfloat16, wmma::row_major> af;
                    wmma::load_matrix_sync(af, Ap + (wm * 32 + i * 16) * 72 + ks * 16, 72);
                    wmma::mma_sync(cf[i][0], af, bf[0], cf[i][0]);
                    wmma::mma_sync(cf[i][1], af, bf[1], cf[i][1]);
                }
            }
            __syncthreads();
        }

        #pragma unroll
        for (int i = 0; i < 2; i++)
            #pragma unroll
            for (int j = 0; j < 2; j++)
                wmma::store_matrix_sync(Cs + (wm * 32 + i * 16) * 72 + wn * 32 + j * 16,
                                        cf[i][j], 72, wmma::mem_row_major);
        __syncthreads();

        if (tid < 128) {
            const float* crow = Cs + tid * 72;
            #pragma unroll
            for (int j = 0; j < 64; j++) {
                float key = c2S[j] - 2.f * crow[j];
                uint32_t u = __float_as_uint(key);
                u = (u & 0x80000000u) ? ~u : (u | 0x80000000u);   // order-preserving
                uint32_t cand = (u & 0xFFFFF000u) | (uint32_t)(n0 + j);
                ins8(cand, s8);
            }
        }
        __syncthreads();
    }

    // exact rescoring of the 8 candidates
    if (tid < 128) {
        size_t r = (size_t)r0 + tid;
        const unsigned short* ph = gPhiT + r * PSTR;
        const float BIG = 3.4e38f;
        float t0 = BIG, t1 = BIG, t2 = BIG;
        #pragma unroll 1
        for (int cidx = 0; cidx < 8; cidx++) {
            int n = (int)(s8[cidx] & 0xFFFu);
            const unsigned short* cr = gCt + (size_t)n * PSTR;
            float dot = 0.f;
            #pragma unroll 4
            for (int k8 = 0; k8 < KCP / 8; k8++) {
                uint4 phv = *(const uint4*)(ph + k8 * 8);
                uint4 plv = *(const uint4*)(ph + KCP + k8 * 8);
                uint4 chv = *(const uint4*)(cr + k8 * 8);
                uint4 clv = *(const uint4*)(cr + KCP + k8 * 8);
                const uint32_t pw[4] = {phv.x, phv.y, phv.z, phv.w};
                const uint32_t lw[4] = {plv.x, plv.y, plv.z, plv.w};
                const uint32_t cw[4] = {chv.x, chv.y, chv.z, chv.w};
                const uint32_t dw[4] = {clv.x, clv.y, clv.z, clv.w};
                #pragma unroll
                for (int q = 0; q < 4; q++) {
                    float2 p_h = unpk(pw[q]), p_l = unpk(lw[q]);
                    float2 c_h = unpk(cw[q]), c_l = unpk(dw[q]);
                    dot = fmaf(p_h.x + p_l.x, c_h.x + c_l.x, dot);
                    dot = fmaf(p_h.y + p_l.y, c_h.y + c_l.y, dot);
                }
            }
            float key = g_cent2[n] - 2.f * dot;
            ins3(key, t0, t1, t2);
        }
        float f2 = g_feat2[r];
        float d0 = sqrtf(fmaxf(f2 + t0, 0.f));
        float d1 = sqrtf(fmaxf(f2 + t1, 0.f));
        float d2 = sqrtf(fmaxf(f2 + t2, 0.f));
        float sm = 1.f / (1.f + expf(d0 - d1) + expf(d0 - d2));
        out[r] = d0 * sm;
    }
}

// ---------------- launch ----------------
extern "C" void kernel_launch(void* const* d_in, const int* in_sizes, int n_in,
                              void* d_out, int out_size) {
    (void)in_sizes; (void)n_in; (void)out_size;
    const float* p0     = (const float*)d_in[0];
    const float* p1     = (const float*)d_in[1];
    const float* p2     = (const float*)d_in[2];
    const float* conv_w = (const float*)d_in[3];
    const float* conv_b = (const float*)d_in[4];
    const float* Cmat   = (const float*)d_in[5];
    float* out = (float*)d_out;

    {
        int t1 = BZ * C1N * 28 * 28;
        pool_kernel<<<(t1 + 255) / 256, 256>>>(p1, t1, 28, 0);
        int t2 = BZ * C2N * 14 * 14;
        pool_kernel<<<(t2 + 255) / 256, 256>>>(p2, t2, 14, 1);
    }
    prepW_kernel<<<(DOUT * KBP + 255) / 256, 256>>>(conv_w);
    {
        dim3 grid(NC / 64, KCP / 64);
        prepC_kernel<<<grid, 256>>>(Cmat);
    }
    cent2_kernel<<<(NC * 8 + 255) / 256, 256>>>(Cmat);
    {
        dim3 grid(RR / 64, KBP / 64);
        buildx_kernel<<<grid, 256>>>(p0);
    }
    {
        cudaFuncSetAttribute(gemmB_kernel, cudaFuncAttributeMaxDynamicSharedMemorySize, B_SMEM);
        gemmB_kernel<<<RR / 128, 256, B_SMEM>>>(conv_b);
    }
    {
        cudaFuncSetAttribute(gemmC_kernel, cudaFuncAttributeMaxDynamicSharedMemorySize, C_SMEM);
        gemmC_kernel<<<RR / 128, 256, C_SMEM>>>(out);
    }
}

// round 15
// speedup vs baseline: 1.4452x; 1.4452x over previous
#include <cuda_runtime.h>
#include <cuda_bf16.h>
#include <mma.h>
#include <math.h>
#include <stdint.h>

// ---------------- problem constants ----------------
#define BZ    8
#define HH    56
#define WW    56
#define HWP   3136
#define RR    25088       // BZ*HWP rows
#define C0N   256
#define C1N   512
#define C2N   1024
#define CIN   1794
#define DOUT  448
#define NC    3136

#define KBP   1856        // gemmB K padded (29*64)
#define WSTR  (2*KBP)     // W: hi plane + lo plane
#define KCP   448         // gemmC K (7*64)
#define PSTR  (2*KCP)     // phi / C stride (hi+lo planes)

#define SEG_B (KBP/64)    // 29
#define SEG_C (KCP/64)    // 7
#define NCH_B (2*SEG_B)   // 58  (X-lo product dropped — R10-validated error class)

// smem layout (bytes)
#define FB_A0  0
#define FB_A1  18432
#define FB_B0  36864
#define FB_B1  46080
#define FB_CS  55296            // 128*72*4 = 36864
#define FB_AUX 92160            // bias / cent2 staging (64 floats)
#define B_SMEM 148480
#define C_SMEM 98304

// ---------------- scratch ----------------
__device__ float g_pool1[BZ * C1N * 28 * 28];
__device__ float g_pool2[BZ * C2N * 14 * 14];
__device__ float g_feat2[RR];
__device__ float g_cent2[NC];
__device__ __align__(16) unsigned short gXt[(size_t)RR * KBP];     // 93 MB (hi only)
__device__ __align__(16) unsigned short gWt[(size_t)DOUT * WSTR];
__device__ __align__(16) unsigned short gPhiT[(size_t)RR * PSTR];
__device__ __align__(16) unsigned short gCt[(size_t)NC * PSTR];

// ---------------- helpers ----------------
__device__ __forceinline__ unsigned short f2bf(float x) {
    __nv_bfloat16 h = __float2bfloat16(x);
    unsigned short u; memcpy(&u, &h, 2); return u;
}
__device__ __forceinline__ float bf2f(unsigned short u) {
    return __uint_as_float((unsigned)u << 16);
}
__device__ __forceinline__ void ins3(float v, float& a, float& b, float& c) {
    if (v < c) {
        if (v < b) { c = b; if (v < a) { b = a; a = v; } else b = v; }
        else c = v;
    }
}
__device__ __forceinline__ void ins8(uint32_t v, uint32_t* s) {
    if (v < s[7]) {
        s[7] = v;
        #pragma unroll
        for (int i = 7; i > 0; i--) {
            if (s[i] < s[i - 1]) { uint32_t t = s[i]; s[i] = s[i - 1]; s[i - 1] = t; }
        }
    }
}
__device__ __forceinline__ float2 unpk(uint32_t w) {
    return make_float2(__uint_as_float(w << 16), __uint_as_float(w & 0xFFFF0000u));
}

__device__ __forceinline__ float bilin(const float* __restrict__ ch, int S, float u, float v) {
    int y0 = (int)floorf(u); float fy = u - (float)y0;
    int x0 = (int)floorf(v); float fx = v - (float)x0;
    int y0c = min(max(y0, 0), S - 1);
    int y1c = min(max(y0 + 1, 0), S - 1);
    int x0c = min(max(x0, 0), S - 1);
    int x1c = min(max(x0 + 1, 0), S - 1);
    float a = ch[y0c * S + x0c], b = ch[y0c * S + x1c];
    float c = ch[y1c * S + x0c], d = ch[y1c * S + x1c];
    return (1.f - fy) * ((1.f - fx) * a + fx * b) + fy * ((1.f - fx) * c + fx * d);
}

// stage NROWS x 64 bf16 into padded stride-72 smem (LDG+STS)
template<int NROWS>
__device__ __forceinline__ void fstage(const unsigned short* __restrict__ src,
                                       size_t rstride, unsigned short* dst, int tid) {
    #pragma unroll
    for (int s = 0; s < NROWS * 8 / 256; s++) {
        int l = tid + s * 256;
        int row = l >> 3, c8 = l & 7;
        uint4 v = *(const uint4*)(src + (size_t)row * rstride + c8 * 8);
        *(uint4*)(dst + row * 72 + c8 * 8) = v;
    }
}

// ---------------- stage 1: pools for p1/p2 ----------------
__global__ void pool_kernel(const float* __restrict__ in, int total, int S, int which) {
    int idx = blockIdx.x * 256 + threadIdx.x;
    if (idx >= total) return;
    int x = idx % S, y = (idx / S) % S, bc = idx / (S * S);
    const float* p = in + (size_t)bc * S * S;
    float s = 0.f;
    #pragma unroll
    for (int dy = -1; dy <= 1; dy++) {
        int yy = y + dy; if ((unsigned)yy >= (unsigned)S) continue;
        #pragma unroll
        for (int dx = -1; dx <= 1; dx++) {
            int xx = x + dx; if ((unsigned)xx >= (unsigned)S) continue;
            s += p[yy * S + xx];
        }
    }
    (which ? g_pool2 : g_pool1)[idx] = s * (1.f / 9.f);
}

// ---------------- stage 2: weight/center packing ----------------
__global__ void prepW_kernel(const float* __restrict__ w) {
    int idx = blockIdx.x * 256 + threadIdx.x;
    if (idx >= DOUT * KBP) return;
    int o = idx / KBP, k = idx - o * KBP;
    float v = (k < CIN) ? w[o * CIN + k] : 0.f;
    unsigned short h = f2bf(v);
    gWt[(size_t)o * WSTR + k] = h;
    gWt[(size_t)o * WSTR + KBP + k] = f2bf(v - bf2f(h));
}

__global__ void prepC_kernel(const float* __restrict__ Cmat) {
    __shared__ float s[64][65];
    int n0 = blockIdx.x * 64;
    int k0 = blockIdx.y * 64;
    int tid = threadIdx.x;
    #pragma unroll
    for (int it = 0; it < 16; it++) {
        int l = tid + it * 256;
        int kk = l >> 6, nn = l & 63;
        s[kk][nn] = Cmat[(size_t)(k0 + kk) * NC + n0 + nn];
    }
    __syncthreads();
    #pragma unroll
    for (int it = 0; it < 2; it++) {
        int sg = tid + it * 256;
        int nn = sg >> 3, c8 = (sg & 7) * 8;
        unsigned hw[4], lw[4];
        #pragma unroll
        for (int j = 0; j < 8; j += 2) {
            float v0 = s[c8 + j][nn], v1 = s[c8 + j + 1][nn];
            unsigned short h0 = f2bf(v0), h1 = f2bf(v1);
            unsigned short l0 = f2bf(v0 - bf2f(h0)), l1 = f2bf(v1 - bf2f(h1));
            hw[j >> 1] = (unsigned)h0 | ((unsigned)h1 << 16);
            lw[j >> 1] = (unsigned)l0 | ((unsigned)l1 << 16);
        }
        size_t base = (size_t)(n0 + nn) * PSTR + k0 + c8;
        *(uint4*)(gCt + base)       = make_uint4(hw[0], hw[1], hw[2], hw[3]);
        *(uint4*)(gCt + base + KCP) = make_uint4(lw[0], lw[1], lw[2], lw[3]);
    }
}

__global__ void cent2_kernel(const float* __restrict__ Cmat) {
    int gid = blockIdx.x * 256 + threadIdx.x;
    int n = gid >> 3, part = gid & 7;
    if (n >= NC) return;
    float s = 0.f;
    for (int o = part; o < DOUT; o += 8) {
        float v = Cmat[(size_t)o * NC + n];
        s = fmaf(v, v, s);
    }
    s += __shfl_xor_sync(0xFFFFFFFFu, s, 1);
    s += __shfl_xor_sync(0xFFFFFFFFu, s, 2);
    s += __shfl_xor_sync(0xFFFFFFFFu, s, 4);
    if (part == 0) g_cent2[n] = s;
}

// ---------------- stage 3: build X row-major bf16 (hi plane only) ----------------
__global__ void buildx_kernel(const float* __restrict__ p0) {
    __shared__ float s[64][65];
    int rt0 = blockIdx.x * 64;
    int kt0 = blockIdx.y * 64;
    int tid = threadIdx.x;
    int rr = tid & 63;
    int r = rt0 + rr;
    int b = r / HWP;
    int pix = r - b * HWP;
    int h = pix / WW, w = pix - h * WW;

    #pragma unroll 1
    for (int i = 0; i < 16; i++) {
        int kk = (tid >> 6) * 16 + i;
        int k = kt0 + kk;
        float val;
        if (k < C0N) {
            const float* p = p0 + (size_t)(b * C0N + k) * HWP;
            float acc = 0.f;
            #pragma unroll
            for (int dy = -1; dy <= 1; dy++) {
                int y = h + dy; if ((unsigned)y >= (unsigned)HH) continue;
                #pragma unroll
                for (int dx = -1; dx <= 1; dx++) {
                    int x = w + dx; if ((unsigned)x >= (unsigned)WW) continue;
                    acc += p[y * WW + x];
                }
            }
            val = acc * (1.f / 9.f);
        } else if (k < C0N + C1N) {
            const float* ch = g_pool1 + (size_t)(b * C1N + (k - C0N)) * 784;
            val = bilin(ch, 28, h * 0.5f - 0.25f, w * 0.5f - 0.25f);
        } else if (k < C0N + C1N + C2N) {
            const float* ch = g_pool2 + (size_t)(b * C2N + (k - C0N - C1N)) * 196;
            val = bilin(ch, 14, h * 0.25f - 0.375f, w * 0.25f - 0.375f);
        } else if (k == 1792) {
            val = (float)h * (2.f / 55.f) - 1.f;
        } else if (k == 1793) {
            val = (float)w * (2.f / 55.f) - 1.f;
        } else {
            val = 0.f;
        }
        s[kk][rr] = val;
    }
    __syncthreads();

    #pragma unroll
    for (int it = 0; it < 2; it++) {
        int sg = tid + it * 256;
        int row = sg >> 3, c8 = (sg & 7) * 8;
        unsigned hw[4];
        #pragma unroll
        for (int j = 0; j < 8; j += 2) {
            float v0 = s[c8 + j][row], v1 = s[c8 + j + 1][row];
            hw[j >> 1] = (unsigned)f2bf(v0) | ((unsigned)f2bf(v1) << 16);
        }
        size_t base = (size_t)(rt0 + row) * KBP + kt0 + c8;
        *(uint4*)(gXt + base) = make_uint4(hw[0], hw[1], hw[2], hw[3]);
    }
}

// ==================================================================
// GEMM-B: phi ~= Xhi*(Whi+Wlo) + bias; fused feat2 + bf16 hi/lo store.
// block 128x64, 7 n-tiles, warp tile 32x32, 58 chunks (2 products).
// ==================================================================
__global__ void __launch_bounds__(256)
gemmB_kernel(const float* __restrict__ bias) {
    using namespace nvcuda;
    extern __shared__ char smc[];
    float* Cs = (float*)(smc + FB_CS);
    float* biasS = (float*)(smc + FB_AUX);
    unsigned short* Abuf[2] = {(unsigned short*)(smc + FB_A0), (unsigned short*)(smc + FB_A1)};
    unsigned short* Bbuf[2] = {(unsigned short*)(smc + FB_B0), (unsigned short*)(smc + FB_B1)};
    int tid = threadIdx.x, wid = tid >> 5;
    int wm = wid & 3, wn = wid >> 2;
    int r0 = blockIdx.x * 128;
    float ss = 0.f;

    #pragma unroll 1
    for (int nt = 0; nt < DOUT / 64; nt++) {
        int n0 = nt * 64;
        if (tid < 64) biasS[tid] = bias[n0 + tid];

        wmma::fragment<wmma::accumulator, 16, 16, 16, float> cf[2][2];
        #pragma unroll
        for (int i = 0; i < 2; i++)
            #pragma unroll
            for (int j = 0; j < 2; j++) wmma::fill_fragment(cf[i][j], 0.f);

        fstage<128>(gXt + (size_t)r0 * KBP, KBP, Abuf[0], tid);
        fstage<64>(gWt + (size_t)n0 * WSTR, WSTR, Bbuf[0], tid);
        __syncthreads();

        #pragma unroll 1
        for (int c = 0; c < NCH_B; c++) {
            if (c + 1 < NCH_B) {
                int c1 = c + 1;
                int seg = c1 / SEG_B;                 // 0: W-hi, 1: W-lo
                int kb = (c1 - seg * SEG_B) * 64;
                int pb = seg ? KBP : 0;
                fstage<128>(gXt + (size_t)r0 * KBP + kb, KBP, Abuf[c1 & 1], tid);
                fstage<64>(gWt + (size_t)n0 * WSTR + pb + kb, WSTR, Bbuf[c1 & 1], tid);
            }
            const __nv_bfloat16* Ap = (const __nv_bfloat16*)Abuf[c & 1];
            const __nv_bfloat16* Bp = (const __nv_bfloat16*)Bbuf[c & 1];
            #pragma unroll
            for (int ks = 0; ks < 4; ks++) {
                wmma::fragment<wmma::matrix_b, 16, 16, 16, __nv_bfloat16, wmma::col_major> bf[2];
                wmma::load_matrix_sync(bf[0], Bp + (wn * 32) * 72 + ks * 16, 72);
                wmma::load_matrix_sync(bf[1], Bp + (wn * 32 + 16) * 72 + ks * 16, 72);
                #pragma unroll
                for (int i = 0; i < 2; i++) {
                    wmma::fragment<wmma::matrix_a, 16, 16, 16, __nv_bfloat16, wmma::row_major> af;
                    wmma::load_matrix_sync(af, Ap + (wm * 32 + i * 16) * 72 + ks * 16, 72);
                    wmma::mma_sync(cf[i][0], af, bf[0], cf[i][0]);
                    wmma::mma_sync(cf[i][1], af, bf[1], cf[i][1]);
                }
            }
            __syncthreads();
        }

        #pragma unroll
        for (int i = 0; i < 2; i++)
            #pragma unroll
            for (int j = 0; j < 2; j++)
                wmma::store_matrix_sync(Cs + (wm * 32 + i * 16) * 72 + wn * 32 + j * 16,
                                        cf[i][j], 72, wmma::mem_row_major);
        __syncthreads();

        if (tid < 128) {
            const float* crow = Cs + tid * 72;
            size_t r = (size_t)r0 + tid;
            unsigned hw[32], lw[32];
            #pragma unroll
            for (int j = 0; j < 64; j += 2) {
                float v0 = crow[j] + biasS[j];
                float v1 = crow[j + 1] + biasS[j + 1];
                ss = fmaf(v0, v0, ss);
                ss = fmaf(v1, v1, ss);
                unsigned short h0 = f2bf(v0), h1 = f2bf(v1);
                unsigned short l0 = f2bf(v0 - bf2f(h0)), l1 = f2bf(v1 - bf2f(h1));
                hw[j >> 1] = (unsigned)h0 | ((unsigned)h1 << 16);
                lw[j >> 1] = (unsigned)l0 | ((unsigned)l1 << 16);
            }
            uint4* dh = (uint4*)(gPhiT + r * PSTR + n0);
            uint4* dl = (uint4*)(gPhiT + r * PSTR + KCP + n0);
            #pragma unroll
            for (int q = 0; q < 8; q++) {
                dh[q] = make_uint4(hw[q * 4], hw[q * 4 + 1], hw[q * 4 + 2], hw[q * 4 + 3]);
                dl[q] = make_uint4(lw[q * 4], lw[q * 4 + 1], lw[q * 4 + 2], lw[q * 4 + 3]);
            }
        }
        __syncthreads();
    }
    if (tid < 128) g_feat2[r0 + tid] = ss;
}

// ==================================================================
// GEMM-C: approximate selection (phi_hi x C_hi, 7 chunks/tile),
// per-row top-8, exact rescoring + softmin. (R12-proven)
// ==================================================================
__global__ void __launch_bounds__(256)
gemmC_kernel(float* __restrict__ out) {
    using namespace nvcuda;
    extern __shared__ char smc[];
    float* Cs = (float*)(smc + FB_CS);
    float* c2S = (float*)(smc + FB_AUX);
    unsigned short* Abuf[2] = {(unsigned short*)(smc + FB_A0), (unsigned short*)(smc + FB_A1)};
    unsigned short* Bbuf[2] = {(unsigned short*)(smc + FB_B0), (unsigned short*)(smc + FB_B1)};
    int tid = threadIdx.x, wid = tid >> 5;
    int wm = wid & 3, wn = wid >> 2;
    int r0 = blockIdx.x * 128;

    uint32_t s8[8];
    #pragma unroll
    for (int i = 0; i < 8; i++) s8[i] = 0xFFFFFFFFu;

    #pragma unroll 1
    for (int nt = 0; nt < NC / 64; nt++) {
        int n0 = nt * 64;
        if (tid < 64) c2S[tid] = g_cent2[n0 + tid];

        wmma::fragment<wmma::accumulator, 16, 16, 16, float> cf[2][2];
        #pragma unroll
        for (int i = 0; i < 2; i++)
            #pragma unroll
            for (int j = 0; j < 2; j++) wmma::fill_fragment(cf[i][j], 0.f);

        fstage<128>(gPhiT + (size_t)r0 * PSTR, PSTR, Abuf[0], tid);
        fstage<64>(gCt + (size_t)n0 * PSTR, PSTR, Bbuf[0], tid);
        __syncthreads();

        #pragma unroll 1
        for (int c = 0; c < SEG_C; c++) {
            if (c + 1 < SEG_C) {
                int kb = (c + 1) * 64;
                fstage<128>(gPhiT + (size_t)r0 * PSTR + kb, PSTR, Abuf[(c + 1) & 1], tid);
                fstage<64>(gCt + (size_t)n0 * PSTR + kb, PSTR, Bbuf[(c + 1) & 1], tid);
            }
            const __nv_bfloat16* Ap = (const __nv_bfloat16*)Abuf[c & 1];
            const __nv_bfloat16* Bp = (const __nv_bfloat16*)Bbuf[c & 1];
            #pragma unroll
            for (int ks = 0; ks < 4; ks++) {
                wmma::fragment<wmma::matrix_b, 16, 16, 16, __nv_bfloat16, wmma::col_major> bf[2];
                wmma::load_matrix_sync(bf[0], Bp + (wn * 32) * 72 + ks * 16, 72);
                wmma::load_matrix_sync(bf[1], Bp + (wn * 32 + 16) * 72 + ks * 16, 72);
                #pragma unroll
                for (int i = 0; i < 2; i++) {
                    wmma::fragment<wmma::matrix_a, 16, 16, 16, __nv_bfloat16, wmma::row_major> af;
                    wmma::load_matrix_sync(af, Ap + (wm * 32 + i * 16) * 72 + ks * 16, 72);
                    wmma::mma_sync(cf[i][0], af, bf[0], cf[i][0]);
                    wmma::mma_sync(cf[i][1], af, bf[1], cf[i][1]);
                }
            }
            __syncthreads();
        }

        #pragma unroll
        for (int i = 0; i < 2; i++)
            #pragma unroll
            for (int j = 0; j < 2; j++)
                wmma::store_matrix_sync(Cs + (wm * 32 + i * 16) * 72 + wn * 32 + j * 16,
                                        cf[i][j], 72, wmma::mem_row_major);
        __syncthreads();

        if (tid < 128) {
            const float* crow = Cs + tid * 72;
            #pragma unroll
            for (int j = 0; j < 64; j++) {
                float key = c2S[j] - 2.f * crow[j];
                uint32_t u = __float_as_uint(key);
                u = (u & 0x80000000u) ? ~u : (u | 0x80000000u);
                uint32_t cand = (u & 0xFFFFF000u) | (uint32_t)(n0 + j);
                ins8(cand, s8);
            }
        }
        __syncthreads();
    }

    if (tid < 128) {
        size_t r = (size_t)r0 + tid;
        const unsigned short* ph = gPhiT + r * PSTR;
        const float BIG = 3.4e38f;
        float t0 = BIG, t1 = BIG, t2 = BIG;
        #pragma unroll 1
        for (int cidx = 0; cidx < 8; cidx++) {
            int n = (int)(s8[cidx] & 0xFFFu);
            const unsigned short* cr = gCt + (size_t)n * PSTR;
            float dot = 0.f;
            #pragma unroll 4
            for (int k8 = 0; k8 < KCP / 8; k8++) {
                uint4 phv = *(const uint4*)(ph + k8 * 8);
                uint4 plv = *(const uint4*)(ph + KCP + k8 * 8);
                uint4 chv = *(const uint4*)(cr + k8 * 8);
                uint4 clv = *(const uint4*)(cr + KCP + k8 * 8);
                const uint32_t pw[4] = {phv.x, phv.y, phv.z, phv.w};
                const uint32_t lw[4] = {plv.x, plv.y, plv.z, plv.w};
                const uint32_t cw[4] = {chv.x, chv.y, chv.z, chv.w};
                const uint32_t dw[4] = {clv.x, clv.y, clv.z, clv.w};
                #pragma unroll
                for (int q = 0; q < 4; q++) {
                    float2 p_h = unpk(pw[q]), p_l = unpk(lw[q]);
                    float2 c_h = unpk(cw[q]), c_l = unpk(dw[q]);
                    dot = fmaf(p_h.x + p_l.x, c_h.x + c_l.x, dot);
                    dot = fmaf(p_h.y + p_l.y, c_h.y + c_l.y, dot);
                }
            }
            float key = g_cent2[n] - 2.f * dot;
            ins3(key, t0, t1, t2);
        }
        float f2 = g_feat2[r];
        float d0 = sqrtf(fmaxf(f2 + t0, 0.f));
        float d1 = sqrtf(fmaxf(f2 + t1, 0.f));
        float d2 = sqrtf(fmaxf(f2 + t2, 0.f));
        float sm = 1.f / (1.f + expf(d0 - d1) + expf(d0 - d2));
        out[r] = d0 * sm;
    }
}

// ---------------- launch ----------------
extern "C" void kernel_launch(void* const* d_in, const int* in_sizes, int n_in,
                              void* d_out, int out_size) {
    (void)in_sizes; (void)n_in; (void)out_size;
    const float* p0     = (const float*)d_in[0];
    const float* p1     = (const float*)d_in[1];
    const float* p2     = (const float*)d_in[2];
    const float* conv_w = (const float*)d_in[3];
    const float* conv_b = (const float*)d_in[4];
    const float* Cmat   = (const float*)d_in[5];
    float* out = (float*)d_out;

    {
        int t1 = BZ * C1N * 28 * 28;
        pool_kernel<<<(t1 + 255) / 256, 256>>>(p1, t1, 28, 0);
        int t2 = BZ * C2N * 14 * 14;
        pool_kernel<<<(t2 + 255) / 256, 256>>>(p2, t2, 14, 1);
    }
    prepW_kernel<<<(DOUT * KBP + 255) / 256, 256>>>(conv_w);
    {
        dim3 grid(NC / 64, KCP / 64);
        prepC_kernel<<<grid, 256>>>(Cmat);
    }
    cent2_kernel<<<(NC * 8 + 255) / 256, 256>>>(Cmat);
    {
        dim3 grid(RR / 64, KBP / 64);
        buildx_kernel<<<grid, 256>>>(p0);
    }
    {
        cudaFuncSetAttribute(gemmB_kernel, cudaFuncAttributeMaxDynamicSharedMemorySize, B_SMEM);
        gemmB_kernel<<<RR / 128, 256, B_SMEM>>>(conv_b);
    }
    {
        cudaFuncSetAttribute(gemmC_kernel, cudaFuncAttributeMaxDynamicSharedMemorySize, C_SMEM);
        gemmC_kernel<<<RR / 128, 256, C_SMEM>>>(out);
    }
}

// round 16
// speedup vs baseline: 1.9916x; 1.3781x over previous
#include <cuda_runtime.h>
#include <cuda_bf16.h>
#include <mma.h>
#include <math.h>
#include <stdint.h>

// ---------------- problem constants ----------------
#define BZ    8
#define HH    56
#define WW    56
#define HWP   3136
#define RR    25088       // BZ*HWP rows
#define C0N   256
#define C1N   512
#define C2N   1024
#define CIN   1794
#define DOUT  448
#define NC    3136

#define KBP   1856        // gemmB K padded (29*64)
#define KCP   448         // gemmC K (7*64)
#define PSTR  (2*KCP)     // phi / C stride (hi+lo planes)

#define SEG_B (KBP/64)    // 29
#define SEG_C (KCP/64)    // 7
#define NCH_B SEG_B       // 29  (pure bf16 product: X-lo AND W-lo dropped)

// smem layout (bytes)
#define FB_A0  0
#define FB_A1  18432
#define FB_B0  36864
#define FB_B1  46080
#define FB_CS  55296            // 128*72*4 = 36864
#define FB_AUX 92160            // bias / cent2 staging (64 floats)
#define B_SMEM 148480
#define C_SMEM 98304

// ---------------- scratch ----------------
__device__ float g_pool1[BZ * C1N * 28 * 28];
__device__ float g_pool2[BZ * C2N * 14 * 14];
__device__ float g_feat2[RR];
__device__ float g_cent2[NC];
__device__ __align__(16) unsigned short gXt[(size_t)RR * KBP];     // 93 MB (hi only)
__device__ __align__(16) unsigned short gWt[(size_t)DOUT * KBP];   // hi only
__device__ __align__(16) unsigned short gPhiT[(size_t)RR * PSTR];
__device__ __align__(16) unsigned short gCt[(size_t)NC * PSTR];

// ---------------- helpers ----------------
__device__ __forceinline__ unsigned short f2bf(float x) {
    __nv_bfloat16 h = __float2bfloat16(x);
    unsigned short u; memcpy(&u, &h, 2); return u;
}
__device__ __forceinline__ float bf2f(unsigned short u) {
    return __uint_as_float((unsigned)u << 16);
}
__device__ __forceinline__ void ins3(float v, float& a, float& b, float& c) {
    if (v < c) {
        if (v < b) { c = b; if (v < a) { b = a; a = v; } else b = v; }
        else c = v;
    }
}
__device__ __forceinline__ void ins8(uint32_t v, uint32_t* s) {
    if (v < s[7]) {
        s[7] = v;
        #pragma unroll
        for (int i = 7; i > 0; i--) {
            if (s[i] < s[i - 1]) { uint32_t t = s[i]; s[i] = s[i - 1]; s[i - 1] = t; }
        }
    }
}
__device__ __forceinline__ float2 unpk(uint32_t w) {
    return make_float2(__uint_as_float(w << 16), __uint_as_float(w & 0xFFFF0000u));
}

__device__ __forceinline__ float bilin(const float* __restrict__ ch, int S, float u, float v) {
    int y0 = (int)floorf(u); float fy = u - (float)y0;
    int x0 = (int)floorf(v); float fx = v - (float)x0;
    int y0c = min(max(y0, 0), S - 1);
    int y1c = min(max(y0 + 1, 0), S - 1);
    int x0c = min(max(x0, 0), S - 1);
    int x1c = min(max(x0 + 1, 0), S - 1);
    float a = ch[y0c * S + x0c], b = ch[y0c * S + x1c];
    float c = ch[y1c * S + x0c], d = ch[y1c * S + x1c];
    return (1.f - fy) * ((1.f - fx) * a + fx * b) + fy * ((1.f - fx) * c + fx * d);
}

// stage NROWS x 64 bf16 into padded stride-72 smem (LDG+STS)
template<int NROWS>
__device__ __forceinline__ void fstage(const unsigned short* __restrict__ src,
                                       size_t rstride, unsigned short* dst, int tid) {
    #pragma unroll
    for (int s = 0; s < NROWS * 8 / 256; s++) {
        int l = tid + s * 256;
        int row = l >> 3, c8 = l & 7;
        uint4 v = *(const uint4*)(src + (size_t)row * rstride + c8 * 8);
        *(uint4*)(dst + row * 72 + c8 * 8) = v;
    }
}

// ---------------- stage 1: pools for p1/p2 ----------------
__global__ void pool_kernel(const float* __restrict__ in, int total, int S, int which) {
    int idx = blockIdx.x * 256 + threadIdx.x;
    if (idx >= total) return;
    int x = idx % S, y = (idx / S) % S, bc = idx / (S * S);
    const float* p = in + (size_t)bc * S * S;
    float s = 0.f;
    #pragma unroll
    for (int dy = -1; dy <= 1; dy++) {
        int yy = y + dy; if ((unsigned)yy >= (unsigned)S) continue;
        #pragma unroll
        for (int dx = -1; dx <= 1; dx++) {
            int xx = x + dx; if ((unsigned)xx >= (unsigned)S) continue;
            s += p[yy * S + xx];
        }
    }
    (which ? g_pool2 : g_pool1)[idx] = s * (1.f / 9.f);
}

// ---------------- stage 2: weight/center packing ----------------
__global__ void prepW_kernel(const float* __restrict__ w) {
    int idx = blockIdx.x * 256 + threadIdx.x;
    if (idx >= DOUT * KBP) return;
    int o = idx / KBP, k = idx - o * KBP;
    float v = (k < CIN) ? w[o * CIN + k] : 0.f;
    gWt[(size_t)o * KBP + k] = f2bf(v);
}

__global__ void prepC_kernel(const float* __restrict__ Cmat) {
    __shared__ float s[64][65];
    int n0 = blockIdx.x * 64;
    int k0 = blockIdx.y * 64;
    int tid = threadIdx.x;
    #pragma unroll
    for (int it = 0; it < 16; it++) {
        int l = tid + it * 256;
        int kk = l >> 6, nn = l & 63;
        s[kk][nn] = Cmat[(size_t)(k0 + kk) * NC + n0 + nn];
    }
    __syncthreads();
    #pragma unroll
    for (int it = 0; it < 2; it++) {
        int sg = tid + it * 256;
        int nn = sg >> 3, c8 = (sg & 7) * 8;
        unsigned hw[4], lw[4];
        #pragma unroll
        for (int j = 0; j < 8; j += 2) {
            float v0 = s[c8 + j][nn], v1 = s[c8 + j + 1][nn];
            unsigned short h0 = f2bf(v0), h1 = f2bf(v1);
            unsigned short l0 = f2bf(v0 - bf2f(h0)), l1 = f2bf(v1 - bf2f(h1));
            hw[j >> 1] = (unsigned)h0 | ((unsigned)h1 << 16);
            lw[j >> 1] = (unsigned)l0 | ((unsigned)l1 << 16);
        }
        size_t base = (size_t)(n0 + nn) * PSTR + k0 + c8;
        *(uint4*)(gCt + base)       = make_uint4(hw[0], hw[1], hw[2], hw[3]);
        *(uint4*)(gCt + base + KCP) = make_uint4(lw[0], lw[1], lw[2], lw[3]);
    }
}

__global__ void cent2_kernel(const float* __restrict__ Cmat) {
    int gid = blockIdx.x * 256 + threadIdx.x;
    int n = gid >> 3, part = gid & 7;
    if (n >= NC) return;
    float s = 0.f;
    for (int o = part; o < DOUT; o += 8) {
        float v = Cmat[(size_t)o * NC + n];
        s = fmaf(v, v, s);
    }
    s += __shfl_xor_sync(0xFFFFFFFFu, s, 1);
    s += __shfl_xor_sync(0xFFFFFFFFu, s, 2);
    s += __shfl_xor_sync(0xFFFFFFFFu, s, 4);
    if (part == 0) g_cent2[n] = s;
}

// ---------------- stage 3: build X row-major bf16 (hi plane only) ----------------
__global__ void buildx_kernel(const float* __restrict__ p0) {
    __shared__ float s[64][65];
    int rt0 = blockIdx.x * 64;
    int kt0 = blockIdx.y * 64;
    int tid = threadIdx.x;
    int rr = tid & 63;
    int r = rt0 + rr;
    int b = r / HWP;
    int pix = r - b * HWP;
    int h = pix / WW, w = pix - h * WW;

    #pragma unroll 1
    for (int i = 0; i < 16; i++) {
        int kk = (tid >> 6) * 16 + i;
        int k = kt0 + kk;
        float val;
        if (k < C0N) {
            const float* p = p0 + (size_t)(b * C0N + k) * HWP;
            float acc = 0.f;
            #pragma unroll
            for (int dy = -1; dy <= 1; dy++) {
                int y = h + dy; if ((unsigned)y >= (unsigned)HH) continue;
                #pragma unroll
                for (int dx = -1; dx <= 1; dx++) {
                    int x = w + dx; if ((unsigned)x >= (unsigned)WW) continue;
                    acc += p[y * WW + x];
                }
            }
            val = acc * (1.f / 9.f);
        } else if (k < C0N + C1N) {
            const float* ch = g_pool1 + (size_t)(b * C1N + (k - C0N)) * 784;
            val = bilin(ch, 28, h * 0.5f - 0.25f, w * 0.5f - 0.25f);
        } else if (k < C0N + C1N + C2N) {
            const float* ch = g_pool2 + (size_t)(b * C2N + (k - C0N - C1N)) * 196;
            val = bilin(ch, 14, h * 0.25f - 0.375f, w * 0.25f - 0.375f);
        } else if (k == 1792) {
            val = (float)h * (2.f / 55.f) - 1.f;
        } else if (k == 1793) {
            val = (float)w * (2.f / 55.f) - 1.f;
        } else {
            val = 0.f;
        }
        s[kk][rr] = val;
    }
    __syncthreads();

    #pragma unroll
    for (int it = 0; it < 2; it++) {
        int sg = tid + it * 256;
        int row = sg >> 3, c8 = (sg & 7) * 8;
        unsigned hw[4];
        #pragma unroll
        for (int j = 0; j < 8; j += 2) {
            float v0 = s[c8 + j][row], v1 = s[c8 + j + 1][row];
            hw[j >> 1] = (unsigned)f2bf(v0) | ((unsigned)f2bf(v1) << 16);
        }
        size_t base = (size_t)(rt0 + row) * KBP + kt0 + c8;
        *(uint4*)(gXt + base) = make_uint4(hw[0], hw[1], hw[2], hw[3]);
    }
}

// ==================================================================
// GEMM-B: phi ~= Xhi*Whi + bias (pure bf16); fused feat2 + bf16
// hi/lo store. block 128x64, 7 n-tiles, warp tile 32x32, 29 chunks.
// ==================================================================
__global__ void __launch_bounds__(256)
gemmB_kernel(const float* __restrict__ bias) {
    using namespace nvcuda;
    extern __shared__ char smc[];
    float* Cs = (float*)(smc + FB_CS);
    float* biasS = (float*)(smc + FB_AUX);
    unsigned short* Abuf[2] = {(unsigned short*)(smc + FB_A0), (unsigned short*)(smc + FB_A1)};
    unsigned short* Bbuf[2] = {(unsigned short*)(smc + FB_B0), (unsigned short*)(smc + FB_B1)};
    int tid = threadIdx.x, wid = tid >> 5;
    int wm = wid & 3, wn = wid >> 2;
    int r0 = blockIdx.x * 128;
    float ss = 0.f;

    #pragma unroll 1
    for (int nt = 0; nt < DOUT / 64; nt++) {
        int n0 = nt * 64;
        if (tid < 64) biasS[tid] = bias[n0 + tid];

        wmma::fragment<wmma::accumulator, 16, 16, 16, float> cf[2][2];
        #pragma unroll
        for (int i = 0; i < 2; i++)
            #pragma unroll
            for (int j = 0; j < 2; j++) wmma::fill_fragment(cf[i][j], 0.f);

        fstage<128>(gXt + (size_t)r0 * KBP, KBP, Abuf[0], tid);
        fstage<64>(gWt + (size_t)n0 * KBP, KBP, Bbuf[0], tid);
        __syncthreads();

        #pragma unroll 1
        for (int c = 0; c < NCH_B; c++) {
            if (c + 1 < NCH_B) {
                int kb = (c + 1) * 64;
                fstage<128>(gXt + (size_t)r0 * KBP + kb, KBP, Abuf[(c + 1) & 1], tid);
                fstage<64>(gWt + (size_t)n0 * KBP + kb, KBP, Bbuf[(c + 1) & 1], tid);
            }
            const __nv_bfloat16* Ap = (const __nv_bfloat16*)Abuf[c & 1];
            const __nv_bfloat16* Bp = (const __nv_bfloat16*)Bbuf[c & 1];
            #pragma unroll
            for (int ks = 0; ks < 4; ks++) {
                wmma::fragment<wmma::matrix_b, 16, 16, 16, __nv_bfloat16, wmma::col_major> bf[2];
                wmma::load_matrix_sync(bf[0], Bp + (wn * 32) * 72 + ks * 16, 72);
                wmma::load_matrix_sync(bf[1], Bp + (wn * 32 + 16) * 72 + ks * 16, 72);
                #pragma unroll
                for (int i = 0; i < 2; i++) {
                    wmma::fragment<wmma::matrix_a, 16, 16, 16, __nv_bfloat16, wmma::row_major> af;
                    wmma::load_matrix_sync(af, Ap + (wm * 32 + i * 16) * 72 + ks * 16, 72);
                    wmma::mma_sync(cf[i][0], af, bf[0], cf[i][0]);
                    wmma::mma_sync(cf[i][1], af, bf[1], cf[i][1]);
                }
            }
            __syncthreads();
        }

        #pragma unroll
        for (int i = 0; i < 2; i++)
            #pragma unroll
            for (int j = 0; j < 2; j++)
                wmma::store_matrix_sync(Cs + (wm * 32 + i * 16) * 72 + wn * 32 + j * 16,
                                        cf[i][j], 72, wmma::mem_row_major);
        __syncthreads();

        if (tid < 128) {
            const float* crow = Cs + tid * 72;
            size_t r = (size_t)r0 + tid;
            unsigned hw[32], lw[32];
            #pragma unroll
            for (int j = 0; j < 64; j += 2) {
                float v0 = crow[j] + biasS[j];
                float v1 = crow[j + 1] + biasS[j + 1];
                ss = fmaf(v0, v0, ss);
                ss = fmaf(v1, v1, ss);
                unsigned short h0 = f2bf(v0), h1 = f2bf(v1);
                unsigned short l0 = f2bf(v0 - bf2f(h0)), l1 = f2bf(v1 - bf2f(h1));
                hw[j >> 1] = (unsigned)h0 | ((unsigned)h1 << 16);
                lw[j >> 1] = (unsigned)l0 | ((unsigned)l1 << 16);
            }
            uint4* dh = (uint4*)(gPhiT + r * PSTR + n0);
            uint4* dl = (uint4*)(gPhiT + r * PSTR + KCP + n0);
            #pragma unroll
            for (int q = 0; q < 8; q++) {
                dh[q] = make_uint4(hw[q * 4], hw[q * 4 + 1], hw[q * 4 + 2], hw[q * 4 + 3]);
                dl[q] = make_uint4(lw[q * 4], lw[q * 4 + 1], lw[q * 4 + 2], lw[q * 4 + 3]);
            }
        }
        __syncthreads();
    }
    if (tid < 128) g_feat2[r0 + tid] = ss;
}

// ==================================================================
// GEMM-C: approximate selection (phi_hi x C_hi, 7 chunks/tile),
// per-row top-8, exact rescoring + softmin. (R12-proven)
// ==================================================================
__global__ void __launch_bounds__(256)
gemmC_kernel(float* __restrict__ out) {
    using namespace nvcuda;
    extern __shared__ char smc[];
    float* Cs = (float*)(smc + FB_CS);
    float* c2S = (float*)(smc + FB_AUX);
    unsigned short* Abuf[2] = {(unsigned short*)(smc + FB_A0), (unsigned short*)(smc + FB_A1)};
    unsigned short* Bbuf[2] = {(unsigned short*)(smc + FB_B0), (unsigned short*)(smc + FB_B1)};
    int tid = threadIdx.x, wid = tid >> 5;
    int wm = wid & 3, wn = wid >> 2;
    int r0 = blockIdx.x * 128;

    uint32_t s8[8];
    #pragma unroll
    for (int i = 0; i < 8; i++) s8[i] = 0xFFFFFFFFu;

    #pragma unroll 1
    for (int nt = 0; nt < NC / 64; nt++) {
        int n0 = nt * 64;
        if (tid < 64) c2S[tid] = g_cent2[n0 + tid];

        wmma::fragment<wmma::accumulator, 16, 16, 16, float> cf[2][2];
        #pragma unroll
        for (int i = 0; i < 2; i++)
            #pragma unroll
            for (int j = 0; j < 2; j++) wmma::fill_fragment(cf[i][j], 0.f);

        fstage<128>(gPhiT + (size_t)r0 * PSTR, PSTR, Abuf[0], tid);
        fstage<64>(gCt + (size_t)n0 * PSTR, PSTR, Bbuf[0], tid);
        __syncthreads();

        #pragma unroll 1
        for (int c = 0; c < SEG_C; c++) {
            if (c + 1 < SEG_C) {
                int kb = (c + 1) * 64;
                fstage<128>(gPhiT + (size_t)r0 * PSTR + kb, PSTR, Abuf[(c + 1) & 1], tid);
                fstage<64>(gCt + (size_t)n0 * PSTR + kb, PSTR, Bbuf[(c + 1) & 1], tid);
            }
            const __nv_bfloat16* Ap = (const __nv_bfloat16*)Abuf[c & 1];
            const __nv_bfloat16* Bp = (const __nv_bfloat16*)Bbuf[c & 1];
            #pragma unroll
            for (int ks = 0; ks < 4; ks++) {
                wmma::fragment<wmma::matrix_b, 16, 16, 16, __nv_bfloat16, wmma::col_major> bf[2];
                wmma::load_matrix_sync(bf[0], Bp + (wn * 32) * 72 + ks * 16, 72);
                wmma::load_matrix_sync(bf[1], Bp + (wn * 32 + 16) * 72 + ks * 16, 72);
                #pragma unroll
                for (int i = 0; i < 2; i++) {
                    wmma::fragment<wmma::matrix_a, 16, 16, 16, __nv_bfloat16, wmma::row_major> af;
                    wmma::load_matrix_sync(af, Ap + (wm * 32 + i * 16) * 72 + ks * 16, 72);
                    wmma::mma_sync(cf[i][0], af, bf[0], cf[i][0]);
                    wmma::mma_sync(cf[i][1], af, bf[1], cf[i][1]);
                }
            }
            __syncthreads();
        }

        #pragma unroll
        for (int i = 0; i < 2; i++)
            #pragma unroll
            for (int j = 0; j < 2; j++)
                wmma::store_matrix_sync(Cs + (wm * 32 + i * 16) * 72 + wn * 32 + j * 16,
                                        cf[i][j], 72, wmma::mem_row_major);
        __syncthreads();

        if (tid < 128) {
            const float* crow = Cs + tid * 72;
            #pragma unroll
            for (int j = 0; j < 64; j++) {
                float key = c2S[j] - 2.f * crow[j];
                uint32_t u = __float_as_uint(key);
                u = (u & 0x80000000u) ? ~u : (u | 0x80000000u);
                uint32_t cand = (u & 0xFFFFF000u) | (uint32_t)(n0 + j);
                ins8(cand, s8);
            }
        }
        __syncthreads();
    }

    if (tid < 128) {
        size_t r = (size_t)r0 + tid;
        const unsigned short* ph = gPhiT + r * PSTR;
        const float BIG = 3.4e38f;
        float t0 = BIG, t1 = BIG, t2 = BIG;
        #pragma unroll 1
        for (int cidx = 0; cidx < 8; cidx++) {
            int n = (int)(s8[cidx] & 0xFFFu);
            const unsigned short* cr = gCt + (size_t)n * PSTR;
            float dot = 0.f;
            #pragma unroll 4
            for (int k8 = 0; k8 < KCP / 8; k8++) {
                uint4 phv = *(const uint4*)(ph + k8 * 8);
                uint4 plv = *(const uint4*)(ph + KCP + k8 * 8);
                uint4 chv = *(const uint4*)(cr + k8 * 8);
                uint4 clv = *(const uint4*)(cr + KCP + k8 * 8);
                const uint32_t pw[4] = {phv.x, phv.y, phv.z, phv.w};
                const uint32_t lw[4] = {plv.x, plv.y, plv.z, plv.w};
                const uint32_t cw[4] = {chv.x, chv.y, chv.z, chv.w};
                const uint32_t dw[4] = {clv.x, clv.y, clv.z, clv.w};
                #pragma unroll
                for (int q = 0; q < 4; q++) {
                    float2 p_h = unpk(pw[q]), p_l = unpk(lw[q]);
                    float2 c_h = unpk(cw[q]), c_l = unpk(dw[q]);
                    dot = fmaf(p_h.x + p_l.x, c_h.x + c_l.x, dot);
                    dot = fmaf(p_h.y + p_l.y, c_h.y + c_l.y, dot);
                }
            }
            float key = g_cent2[n] - 2.f * dot;
            ins3(key, t0, t1, t2);
        }
        float f2 = g_feat2[r];
        float d0 = sqrtf(fmaxf(f2 + t0, 0.f));
        float d1 = sqrtf(fmaxf(f2 + t1, 0.f));
        float d2 = sqrtf(fmaxf(f2 + t2, 0.f));
        float sm = 1.f / (1.f + expf(d0 - d1) + expf(d0 - d2));
        out[r] = d0 * sm;
    }
}

// ---------------- launch ----------------
extern "C" void kernel_launch(void* const* d_in, const int* in_sizes, int n_in,
                              void* d_out, int out_size) {
    (void)in_sizes; (void)n_in; (void)out_size;
    const float* p0     = (const float*)d_in[0];
    const float* p1     = (const float*)d_in[1];
    const float* p2     = (const float*)d_in[2];
    const float* conv_w = (const float*)d_in[3];
    const float* conv_b = (const float*)d_in[4];
    const float* Cmat   = (const float*)d_in[5];
    float* out = (float*)d_out;

    {
        int t1 = BZ * C1N * 28 * 28;
        pool_kernel<<<(t1 + 255) / 256, 256>>>(p1, t1, 28, 0);
        int t2 = BZ * C2N * 14 * 14;
        pool_kernel<<<(t2 + 255) / 256, 256>>>(p2, t2, 14, 1);
    }
    prepW_kernel<<<(DOUT * KBP + 255) / 256, 256>>>(conv_w);
    {
        dim3 grid(NC / 64, KCP / 64);
        prepC_kernel<<<grid, 256>>>(Cmat);
    }
    cent2_kernel<<<(NC * 8 + 255) / 256, 256>>>(Cmat);
    {
        dim3 grid(RR / 64, KBP / 64);
        buildx_kernel<<<grid, 256>>>(p0);
    }
    {
        cudaFuncSetAttribute(gemmB_kernel, cudaFuncAttributeMaxDynamicSharedMemorySize, B_SMEM);
        gemmB_kernel<<<RR / 128, 256, B_SMEM>>>(conv_b);
    }
    {
        cudaFuncSetAttribute(gemmC_kernel, cudaFuncAttributeMaxDynamicSharedMemorySize, C_SMEM);
        gemmC_kernel<<<RR / 128, 256, C_SMEM>>>(out);
    }
}

// round 17
// speedup vs baseline: 2.2515x; 1.1305x over previous
#include <cuda_runtime.h>
#include <cuda_bf16.h>
#include <mma.h>
#include <math.h>
#include <stdint.h>

// ---------------- problem constants ----------------
#define BZ    8
#define HH    56
#define WW    56
#define HWP   3136
#define RR    25088       // BZ*HWP rows
#define C0N   256
#define C1N   512
#define C2N   1024
#define CIN   1794
#define DOUT  448
#define NC    3136

#define KBP   1856        // gemmB K padded (29*64)
#define KCP   448         // gemmC K (7*64)
#define PSTR  (2*KCP)     // phi / C stride (hi+lo planes)

#define SEG_B (KBP/64)    // 29
#define SEG_C (KCP/64)    // 7
#define NCH_B SEG_B       // 29  (pure bf16 product)

// smem layout (bytes) — compact: ~66 KB => target 3 CTAs/SM
#define FB_A0  0          // 128x72 bf16 = 18432
#define FB_A1  18432
#define FB_B0  36864      // 64x72 bf16 = 9216
#define FB_B1  46080
#define FB_SCR 55296      // 8 warps x 1024 B fragment scratch
#define FB_AUX 63488      // bias[448] f32 (1792) / c2S[64] + pad
#define FB_SF  65280      // sfeat[128] f32 (512)
#define SMEM_SZ 65792
// gemmC end-merge candidate buffer reuses FB_A0 (128 rows x 16 u32 = 8192 B)

// ---------------- scratch ----------------
__device__ float g_pool1[BZ * C1N * 28 * 28];
__device__ float g_pool2[BZ * C2N * 14 * 14];
__device__ float g_feat2[RR];
__device__ float g_cent2[NC];
__device__ __align__(16) unsigned short gXt[(size_t)RR * KBP];     // 93 MB (hi only)
__device__ __align__(16) unsigned short gWt[(size_t)DOUT * KBP];   // hi only
__device__ __align__(16) unsigned short gPhiT[(size_t)RR * PSTR];
__device__ __align__(16) unsigned short gCt[(size_t)NC * PSTR];

// ---------------- helpers ----------------
__device__ __forceinline__ unsigned short f2bf(float x) {
    __nv_bfloat16 h = __float2bfloat16(x);
    unsigned short u; memcpy(&u, &h, 2); return u;
}
__device__ __forceinline__ float bf2f(unsigned short u) {
    return __uint_as_float((unsigned)u << 16);
}
__device__ __forceinline__ void ins3(float v, float& a, float& b, float& c) {
    if (v < c) {
        if (v < b) { c = b; if (v < a) { b = a; a = v; } else b = v; }
        else c = v;
    }
}
// top-4 insertion over sorted register array (ascending)
__device__ __forceinline__ void ins4(uint32_t v, uint32_t* s) {
    if (v < s[3]) {
        s[3] = v;
        #pragma unroll
        for (int i = 3; i > 0; i--) {
            if (s[i] < s[i - 1]) { uint32_t t = s[i]; s[i] = s[i - 1]; s[i - 1] = t; }
        }
    }
}
__device__ __forceinline__ float2 unpk(uint32_t w) {
    return make_float2(__uint_as_float(w << 16), __uint_as_float(w & 0xFFFF0000u));
}

__device__ __forceinline__ float bilin(const float* __restrict__ ch, int S, float u, float v) {
    int y0 = (int)floorf(u); float fy = u - (float)y0;
    int x0 = (int)floorf(v); float fx = v - (float)x0;
    int y0c = min(max(y0, 0), S - 1);
    int y1c = min(max(y0 + 1, 0), S - 1);
    int x0c = min(max(x0, 0), S - 1);
    int x1c = min(max(x0 + 1, 0), S - 1);
    float a = ch[y0c * S + x0c], b = ch[y0c * S + x1c];
    float c = ch[y1c * S + x0c], d = ch[y1c * S + x1c];
    return (1.f - fy) * ((1.f - fx) * a + fx * b) + fy * ((1.f - fx) * c + fx * d);
}

// stage NROWS x 64 bf16 into padded stride-72 smem (LDG+STS)
template<int NROWS>
__device__ __forceinline__ void fstage(const unsigned short* __restrict__ src,
                                       size_t rstride, unsigned short* dst, int tid) {
    #pragma unroll
    for (int s = 0; s < NROWS * 8 / 256; s++) {
        int l = tid + s * 256;
        int row = l >> 3, c8 = l & 7;
        uint4 v = *(const uint4*)(src + (size_t)row * rstride + c8 * 8);
        *(uint4*)(dst + row * 72 + c8 * 8) = v;
    }
}

// ---------------- stage 1: pools for p1/p2 ----------------
__global__ void pool_kernel(const float* __restrict__ in, int total, int S, int which) {
    int idx = blockIdx.x * 256 + threadIdx.x;
    if (idx >= total) return;
    int x = idx % S, y = (idx / S) % S, bc = idx / (S * S);
    const float* p = in + (size_t)bc * S * S;
    float s = 0.f;
    #pragma unroll
    for (int dy = -1; dy <= 1; dy++) {
        int yy = y + dy; if ((unsigned)yy >= (unsigned)S) continue;
        #pragma unroll
        for (int dx = -1; dx <= 1; dx++) {
            int xx = x + dx; if ((unsigned)xx >= (unsigned)S) continue;
            s += p[yy * S + xx];
        }
    }
    (which ? g_pool2 : g_pool1)[idx] = s * (1.f / 9.f);
}

// ---------------- stage 2: weight/center packing ----------------
__global__ void prepW_kernel(const float* __restrict__ w) {
    int idx = blockIdx.x * 256 + threadIdx.x;
    if (idx >= DOUT * KBP) return;
    int o = idx / KBP, k = idx - o * KBP;
    float v = (k < CIN) ? w[o * CIN + k] : 0.f;
    gWt[(size_t)o * KBP + k] = f2bf(v);
}

__global__ void prepC_kernel(const float* __restrict__ Cmat) {
    __shared__ float s[64][65];
    int n0 = blockIdx.x * 64;
    int k0 = blockIdx.y * 64;
    int tid = threadIdx.x;
    #pragma unroll
    for (int it = 0; it < 16; it++) {
        int l = tid + it * 256;
        int kk = l >> 6, nn = l & 63;
        s[kk][nn] = Cmat[(size_t)(k0 + kk) * NC + n0 + nn];
    }
    __syncthreads();
    #pragma unroll
    for (int it = 0; it < 2; it++) {
        int sg = tid + it * 256;
        int nn = sg >> 3, c8 = (sg & 7) * 8;
        unsigned hw[4], lw[4];
        #pragma unroll
        for (int j = 0; j < 8; j += 2) {
            float v0 = s[c8 + j][nn], v1 = s[c8 + j + 1][nn];
            unsigned short h0 = f2bf(v0), h1 = f2bf(v1);
            unsigned short l0 = f2bf(v0 - bf2f(h0)), l1 = f2bf(v1 - bf2f(h1));
            hw[j >> 1] = (unsigned)h0 | ((unsigned)h1 << 16);
            lw[j >> 1] = (unsigned)l0 | ((unsigned)l1 << 16);
        }
        size_t base = (size_t)(n0 + nn) * PSTR + k0 + c8;
        *(uint4*)(gCt + base)       = make_uint4(hw[0], hw[1], hw[2], hw[3]);
        *(uint4*)(gCt + base + KCP) = make_uint4(lw[0], lw[1], lw[2], lw[3]);
    }
}

__global__ void cent2_kernel(const float* __restrict__ Cmat) {
    int gid = blockIdx.x * 256 + threadIdx.x;
    int n = gid >> 3, part = gid & 7;
    if (n >= NC) return;
    float s = 0.f;
    for (int o = part; o < DOUT; o += 8) {
        float v = Cmat[(size_t)o * NC + n];
        s = fmaf(v, v, s);
    }
    s += __shfl_xor_sync(0xFFFFFFFFu, s, 1);
    s += __shfl_xor_sync(0xFFFFFFFFu, s, 2);
    s += __shfl_xor_sync(0xFFFFFFFFu, s, 4);
    if (part == 0) g_cent2[n] = s;
}

// ---------------- stage 3: build X row-major bf16 (hi plane only) ----------------
__global__ void buildx_kernel(const float* __restrict__ p0) {
    __shared__ float s[64][65];
    int rt0 = blockIdx.x * 64;
    int kt0 = blockIdx.y * 64;
    int tid = threadIdx.x;
    int rr = tid & 63;
    int r = rt0 + rr;
    int b = r / HWP;
    int pix = r - b * HWP;
    int h = pix / WW, w = pix - h * WW;

    #pragma unroll 1
    for (int i = 0; i < 16; i++) {
        int kk = (tid >> 6) * 16 + i;
        int k = kt0 + kk;
        float val;
        if (k < C0N) {
            const float* p = p0 + (size_t)(b * C0N + k) * HWP;
            float acc = 0.f;
            #pragma unroll
            for (int dy = -1; dy <= 1; dy++) {
                int y = h + dy; if ((unsigned)y >= (unsigned)HH) continue;
                #pragma unroll
                for (int dx = -1; dx <= 1; dx++) {
                    int x = w + dx; if ((unsigned)x >= (unsigned)WW) continue;
                    acc += p[y * WW + x];
                }
            }
            val = acc * (1.f / 9.f);
        } else if (k < C0N + C1N) {
            const float* ch = g_pool1 + (size_t)(b * C1N + (k - C0N)) * 784;
            val = bilin(ch, 28, h * 0.5f - 0.25f, w * 0.5f - 0.25f);
        } else if (k < C0N + C1N + C2N) {
            const float* ch = g_pool2 + (size_t)(b * C2N + (k - C0N - C1N)) * 196;
            val = bilin(ch, 14, h * 0.25f - 0.375f, w * 0.25f - 0.375f);
        } else if (k == 1792) {
            val = (float)h * (2.f / 55.f) - 1.f;
        } else if (k == 1793) {
            val = (float)w * (2.f / 55.f) - 1.f;
        } else {
            val = 0.f;
        }
        s[kk][rr] = val;
    }
    __syncthreads();

    #pragma unroll
    for (int it = 0; it < 2; it++) {
        int sg = tid + it * 256;
        int row = sg >> 3, c8 = (sg & 7) * 8;
        unsigned hw[4];
        #pragma unroll
        for (int j = 0; j < 8; j += 2) {
            float v0 = s[c8 + j][row], v1 = s[c8 + j + 1][row];
            hw[j >> 1] = (unsigned)f2bf(v0) | ((unsigned)f2bf(v1) << 16);
        }
        size_t base = (size_t)(rt0 + row) * KBP + kt0 + c8;
        *(uint4*)(gXt + base) = make_uint4(hw[0], hw[1], hw[2], hw[3]);
    }
}

// ==================================================================
// GEMM-B: phi ~= Xhi*Whi + bias; per-warp fragment-scratch epilogue
// (bias + feat2 + bf16 hi/lo store). block 128x64, warp tile 32x32.
// ==================================================================
__global__ void __launch_bounds__(256)
gemmB_kernel(const float* __restrict__ bias) {
    using namespace nvcuda;
    extern __shared__ char smc[];
    unsigned short* Abuf[2] = {(unsigned short*)(smc + FB_A0), (unsigned short*)(smc + FB_A1)};
    unsigned short* Bbuf[2] = {(unsigned short*)(smc + FB_B0), (unsigned short*)(smc + FB_B1)};
    float* scr = (float*)(smc + FB_SCR) + (threadIdx.x >> 5) * 256;
    float* biasS = (float*)(smc + FB_AUX);       // 448 floats
    float* sfeat = (float*)(smc + FB_SF);        // 128 floats
    int tid = threadIdx.x, wid = tid >> 5, lane = tid & 31;
    int wm = wid & 3, wn = wid >> 2;
    int lrow = lane >> 1, lcol = (lane & 1) * 8;
    int r0 = blockIdx.x * 128;

    if (tid < 128) sfeat[tid] = 0.f;
    for (int c = tid; c < DOUT; c += 256) biasS[c] = bias[c];

    float fp[2] = {0.f, 0.f};

    #pragma unroll 1
    for (int nt = 0; nt < DOUT / 64; nt++) {
        int n0 = nt * 64;

        wmma::fragment<wmma::accumulator, 16, 16, 16, float> cf[2][2];
        #pragma unroll
        for (int i = 0; i < 2; i++)
            #pragma unroll
            for (int j = 0; j < 2; j++) wmma::fill_fragment(cf[i][j], 0.f);

        fstage<128>(gXt + (size_t)r0 * KBP, KBP, Abuf[0], tid);
        fstage<64>(gWt + (size_t)n0 * KBP, KBP, Bbuf[0], tid);
        __syncthreads();

        #pragma unroll 1
        for (int c = 0; c < NCH_B; c++) {
            if (c + 1 < NCH_B) {
                int kb = (c + 1) * 64;
                fstage<128>(gXt + (size_t)r0 * KBP + kb, KBP, Abuf[(c + 1) & 1], tid);
                fstage<64>(gWt + (size_t)n0 * KBP + kb, KBP, Bbuf[(c + 1) & 1], tid);
            }
            const __nv_bfloat16* Ap = (const __nv_bfloat16*)Abuf[c & 1];
            const __nv_bfloat16* Bp = (const __nv_bfloat16*)Bbuf[c & 1];
            #pragma unroll
            for (int ks = 0; ks < 4; ks++) {
                wmma::fragment<wmma::matrix_b, 16, 16, 16, __nv_bfloat16, wmma::col_major> bf[2];
                wmma::load_matrix_sync(bf[0], Bp + (wn * 32) * 72 + ks * 16, 72);
                wmma::load_matrix_sync(bf[1], Bp + (wn * 32 + 16) * 72 + ks * 16, 72);
                #pragma unroll
                for (int i = 0; i < 2; i++) {
                    wmma::fragment<wmma::matrix_a, 16, 16, 16, __nv_bfloat16, wmma::row_major> af;
                    wmma::load_matrix_sync(af, Ap + (wm * 32 + i * 16) * 72 + ks * 16, 72);
                    wmma::mma_sync(cf[i][0], af, bf[0], cf[i][0]);
                    wmma::mma_sync(cf[i][1], af, bf[1], cf[i][1]);
                }
            }
            __syncthreads();
        }

        // per-warp fragment epilogue
        #pragma unroll
        for (int mi = 0; mi < 2; mi++) {
            size_t r = (size_t)r0 + wm * 32 + mi * 16 + lrow;
            #pragma unroll
            for (int nj = 0; nj < 2; nj++) {
                __syncwarp();
                wmma::store_matrix_sync(scr, cf[mi][nj], 16, wmma::mem_row_major);
                __syncwarp();
                int col = n0 + wn * 32 + nj * 16 + lcol;
                const float* sp = scr + lrow * 16 + lcol;
                float4 va = *(const float4*)sp;
                float4 vb = *(const float4*)(sp + 4);
                float v[8] = {va.x + biasS[col], va.y + biasS[col + 1],
                              va.z + biasS[col + 2], va.w + biasS[col + 3],
                              vb.x + biasS[col + 4], vb.y + biasS[col + 5],
                              vb.z + biasS[col + 6], vb.w + biasS[col + 7]};
                unsigned hw[4], lw[4];
                #pragma unroll
                for (int j = 0; j < 8; j += 2) {
                    fp[mi] = fmaf(v[j], v[j], fp[mi]);
                    fp[mi] = fmaf(v[j + 1], v[j + 1], fp[mi]);
                    unsigned short h0 = f2bf(v[j]), h1 = f2bf(v[j + 1]);
                    unsigned short l0 = f2bf(v[j] - bf2f(h0)), l1 = f2bf(v[j + 1] - bf2f(h1));
                    hw[j >> 1] = (unsigned)h0 | ((unsigned)h1 << 16);
                    lw[j >> 1] = (unsigned)l0 | ((unsigned)l1 << 16);
                }
                *(uint4*)(gPhiT + r * PSTR + col) = make_uint4(hw[0], hw[1], hw[2], hw[3]);
                *(uint4*)(gPhiT + r * PSTR + KCP + col) = make_uint4(lw[0], lw[1], lw[2], lw[3]);
            }
        }
        __syncthreads();
    }

    // feat2: pair-sum cols, then across the 2 n-warps
    #pragma unroll
    for (int mi = 0; mi < 2; mi++) {
        fp[mi] += __shfl_xor_sync(0xFFFFFFFFu, fp[mi], 1);
        if ((lane & 1) == 0) atomicAdd(&sfeat[wm * 32 + mi * 16 + lrow], fp[mi]);
    }
    __syncthreads();
    if (tid < 128) g_feat2[r0 + tid] = sfeat[tid];
}

// ==================================================================
// GEMM-C: approx selection (phi_hi x C_hi), per-warp fragment-scratch
// epilogue with per-thread top-4 x 2 rows; end merge (16 cands/row)
// + exact rescore + softmin.
// ==================================================================
__global__ void __launch_bounds__(256)
gemmC_kernel(float* __restrict__ out) {
    using namespace nvcuda;
    extern __shared__ char smc[];
    unsigned short* Abuf[2] = {(unsigned short*)(smc + FB_A0), (unsigned short*)(smc + FB_A1)};
    unsigned short* Bbuf[2] = {(unsigned short*)(smc + FB_B0), (unsigned short*)(smc + FB_B1)};
    float* scr = (float*)(smc + FB_SCR) + (threadIdx.x >> 5) * 256;
    float* c2S = (float*)(smc + FB_AUX);   // 64 floats
    int tid = threadIdx.x, wid = tid >> 5, lane = tid & 31;
    int wm = wid & 3, wn = wid >> 2;
    int lrow = lane >> 1, lcol = (lane & 1) * 8;
    int r0 = blockIdx.x * 128;

    uint32_t s4[2][4];
    #pragma unroll
    for (int mi = 0; mi < 2; mi++)
        #pragma unroll
        for (int q = 0; q < 4; q++) s4[mi][q] = 0xFFFFFFFFu;

    #pragma unroll 1
    for (int nt = 0; nt < NC / 64; nt++) {
        int n0 = nt * 64;
        if (tid < 64) c2S[tid] = g_cent2[n0 + tid];

        wmma::fragment<wmma::accumulator, 16, 16, 16, float> cf[2][2];
        #pragma unroll
        for (int i = 0; i < 2; i++)
            #pragma unroll
            for (int j = 0; j < 2; j++) wmma::fill_fragment(cf[i][j], 0.f);

        fstage<128>(gPhiT + (size_t)r0 * PSTR, PSTR, Abuf[0], tid);
        fstage<64>(gCt + (size_t)n0 * PSTR, PSTR, Bbuf[0], tid);
        __syncthreads();

        #pragma unroll 1
        for (int c = 0; c < SEG_C; c++) {
            if (c + 1 < SEG_C) {
                int kb = (c + 1) * 64;
                fstage<128>(gPhiT + (size_t)r0 * PSTR + kb, PSTR, Abuf[(c + 1) & 1], tid);
                fstage<64>(gCt + (size_t)n0 * PSTR + kb, PSTR, Bbuf[(c + 1) & 1], tid);
            }
            const __nv_bfloat16* Ap = (const __nv_bfloat16*)Abuf[c & 1];
            const __nv_bfloat16* Bp = (const __nv_bfloat16*)Bbuf[c & 1];
            #pragma unroll
            for (int ks = 0; ks < 4; ks++) {
                wmma::fragment<wmma::matrix_b, 16, 16, 16, __nv_bfloat16, wmma::col_major> bf[2];
                wmma::load_matrix_sync(bf[0], Bp + (wn * 32) * 72 + ks * 16, 72);
                wmma::load_matrix_sync(bf[1], Bp + (wn * 32 + 16) * 72 + ks * 16, 72);
                #pragma unroll
                for (int i = 0; i < 2; i++) {
                    wmma::fragment<wmma::matrix_a, 16, 16, 16, __nv_bfloat16, wmma::row_major> af;
                    wmma::load_matrix_sync(af, Ap + (wm * 32 + i * 16) * 72 + ks * 16, 72);
                    wmma::mma_sync(cf[i][0], af, bf[0], cf[i][0]);
                    wmma::mma_sync(cf[i][1], af, bf[1], cf[i][1]);
                }
            }
            __syncthreads();
        }

        // per-warp fragment epilogue: top-4 per (thread, row-half)
        #pragma unroll
        for (int mi = 0; mi < 2; mi++) {
            #pragma unroll
            for (int nj = 0; nj < 2; nj++) {
                __syncwarp();
                wmma::store_matrix_sync(scr, cf[mi][nj], 16, wmma::mem_row_major);
                __syncwarp();
                int coll = wn * 32 + nj * 16 + lcol;   // local col in tile
                const float* sp = scr + lrow * 16 + lcol;
                float4 va = *(const float4*)sp;
                float4 vb = *(const float4*)(sp + 4);
                float vv[8] = {va.x, va.y, va.z, va.w, vb.x, vb.y, vb.z, vb.w};
                #pragma unroll
                for (int q = 0; q < 8; q++) {
                    float key = c2S[coll + q] - 2.f * vv[q];
                    uint32_t u = __float_as_uint(key);
                    u = (u & 0x80000000u) ? ~u : (u | 0x80000000u);
                    ins4((u & 0xFFFFF000u) | (uint32_t)(n0 + coll + q), s4[mi]);
                }
            }
        }
        __syncthreads();   // protect c2S rewrite next tile
    }

    // merge: 16 candidates per row (4 partitions x top-4) via smem (reuse Abuf)
    uint32_t* cand = (uint32_t*)(smc + FB_A0);   // [128][16]
    int slot = wn * 2 + (lane & 1);              // 0..3
    #pragma unroll
    for (int mi = 0; mi < 2; mi++) {
        int row = wm * 32 + mi * 16 + lrow;
        #pragma unroll
        for (int q = 0; q < 4; q++)
            cand[row * 16 + slot * 4 + q] = s4[mi][q];
    }
    __syncthreads();

    if (tid < 128) {
        size_t r = (size_t)r0 + tid;
        const unsigned short* ph = gPhiT + r * PSTR;
        const float BIG = 3.4e38f;
        float t0 = BIG, t1 = BIG, t2 = BIG;
        #pragma unroll 1
        for (int cidx = 0; cidx < 16; cidx++) {
            uint32_t cv = cand[tid * 16 + cidx];
            if (cv == 0xFFFFFFFFu) continue;
            int n = (int)(cv & 0xFFFu);
            const unsigned short* cr = gCt + (size_t)n * PSTR;
            float dot = 0.f;
            #pragma unroll 4
            for (int k8 = 0; k8 < KCP / 8; k8++) {
                uint4 phv = *(const uint4*)(ph + k8 * 8);
                uint4 plv = *(const uint4*)(ph + KCP + k8 * 8);
                uint4 chv = *(const uint4*)(cr + k8 * 8);
                uint4 clv = *(const uint4*)(cr + KCP + k8 * 8);
                const uint32_t pw[4] = {phv.x, phv.y, phv.z, phv.w};
                const uint32_t lw[4] = {plv.x, plv.y, plv.z, plv.w};
                const uint32_t cw[4] = {chv.x, chv.y, chv.z, chv.w};
                const uint32_t dw[4] = {clv.x, clv.y, clv.z, clv.w};
                #pragma unroll
                for (int q = 0; q < 4; q++) {
                    float2 p_h = unpk(pw[q]), p_l = unpk(lw[q]);
                    float2 c_h = unpk(cw[q]), c_l = unpk(dw[q]);
                    dot = fmaf(p_h.x + p_l.x, c_h.x + c_l.x, dot);
                    dot = fmaf(p_h.y + p_l.y, c_h.y + c_l.y, dot);
                }
            }
            float key = g_cent2[n] - 2.f * dot;
            ins3(key, t0, t1, t2);
        }
        float f2 = g_feat2[r];
        float d0 = sqrtf(fmaxf(f2 + t0, 0.f));
        float d1 = sqrtf(fmaxf(f2 + t1, 0.f));
        float d2 = sqrtf(fmaxf(f2 + t2, 0.f));
        float sm = 1.f / (1.f + expf(d0 - d1) + expf(d0 - d2));
        out[r] = d0 * sm;
    }
}

// ---------------- launch ----------------
extern "C" void kernel_launch(void* const* d_in, const int* in_sizes, int n_in,
                              void* d_out, int out_size) {
    (void)in_sizes; (void)n_in; (void)out_size;
    const float* p0     = (const float*)d_in[0];
    const float* p1     = (const float*)d_in[1];
    const float* p2     = (const float*)d_in[2];
    const float* conv_w = (const float*)d_in[3];
    const float* conv_b = (const float*)d_in[4];
    const float* Cmat   = (const float*)d_in[5];
    float* out = (float*)d_out;

    {
        int t1 = BZ * C1N * 28 * 28;
        pool_kernel<<<(t1 + 255) / 256, 256>>>(p1, t1, 28, 0);
        int t2 = BZ * C2N * 14 * 14;
        pool_kernel<<<(t2 + 255) / 256, 256>>>(p2, t2, 14, 1);
    }
    prepW_kernel<<<(DOUT * KBP + 255) / 256, 256>>>(conv_w);
    {
        dim3 grid(NC / 64, KCP / 64);
        prepC_kernel<<<grid, 256>>>(Cmat);
    }
    cent2_kernel<<<(NC * 8 + 255) / 256, 256>>>(Cmat);
    {
        dim3 grid(RR / 64, KBP / 64);
        buildx_kernel<<<grid, 256>>>(p0);
    }
    {
        cudaFuncSetAttribute(gemmB_kernel, cudaFuncAttributeMaxDynamicSharedMemorySize, SMEM_SZ);
        gemmB_kernel<<<RR / 128, 256, SMEM_SZ>>>(conv_b);
    }
    {
        cudaFuncSetAttribute(gemmC_kernel, cudaFuncAttributeMaxDynamicSharedMemorySize, SMEM_SZ);
        gemmC_kernel<<<RR / 128, 256, SMEM_SZ>>>(out);
    }
}